// round 3
// baseline (speedup 1.0000x reference)
#include <cuda_runtime.h>
#include <cuda_bf16.h>

#define Bsz 512
#define Ssz 512
#define Dsz 64
#define Hsz 128
#define Gsz 512
#define KSM 111
#define KREG 17
#define LSTM_SMEM (KSM*Gsz*4 + 4*Hsz*8)

typedef unsigned long long u64;

__device__ float g_pre[(size_t)Bsz * Ssz * Gsz];
__device__ float g_h1[(size_t)Bsz * Ssz * Hsz];
__device__ float g_h2last[Bsz * Hsz];
__device__ float g_whh_t[2 * Hsz * Gsz];
__device__ float g_wih0_t[Dsz * Gsz];
__device__ float g_wih1_t[Hsz * Gsz];
__device__ float g_bias[2 * Gsz];

__device__ __forceinline__ u64 pack2(float x, float y) {
    u64 r; asm("mov.b64 %0, {%1,%2};" : "=l"(r) : "f"(x), "f"(y)); return r;
}
__device__ __forceinline__ void unpack2(u64 v, float &x, float &y) {
    asm("mov.b64 {%0,%1}, %2;" : "=f"(x), "=f"(y) : "l"(v));
}
__device__ __forceinline__ u64 ffma2(u64 a, u64 b, u64 c) {
    u64 d; asm("fma.rn.f32x2 %0, %1, %2, %3;" : "=l"(d) : "l"(a), "l"(b), "l"(c));
    return d;
}
__device__ __forceinline__ float sigmoidf_(float x) {
    return 1.0f / (1.0f + __expf(-x));
}
__device__ __forceinline__ float tanhf_(float x) {
    float e = __expf(-2.0f * fabsf(x));
    float r = __fdividef(1.0f - e, 1.0f + e);
    return copysignf(r, x);
}

__global__ void prep_kernel(const float* __restrict__ Wih0, const float* __restrict__ Whh0,
                            const float* __restrict__ bih0, const float* __restrict__ bhh0,
                            const float* __restrict__ Wih1, const float* __restrict__ Whh1,
                            const float* __restrict__ bih1, const float* __restrict__ bhh1) {
    int tid = blockIdx.x * blockDim.x + threadIdx.x;
    int nt  = gridDim.x * blockDim.x;
    for (int idx = tid; idx < Hsz * Gsz; idx += nt) {
        int k = idx >> 9;
        int jg = idx & 511;
        int j = jg >> 2, g = jg & 3;
        g_whh_t[idx]             = Whh0[(g * Hsz + j) * Hsz + k];
        g_whh_t[Hsz * Gsz + idx] = Whh1[(g * Hsz + j) * Hsz + k];
        {
            int n = idx & 511;
            g_wih1_t[idx] = Wih1[n * Hsz + k];
        }
        if (idx < Dsz * Gsz) {
            int k0 = idx >> 9, n = idx & 511;
            g_wih0_t[idx] = Wih0[n * Dsz + k0];
        }
        if (idx < Gsz) {
            g_bias[idx]       = bih0[idx] + bhh0[idx];
            g_bias[Gsz + idx] = bih1[idx] + bhh1[idx];
        }
    }
}

// C[m][n] = sum_k A[m][k]*Wt[k][n] + bias[n]; BM=BN=128, 256 thr, 8x8 tile.
template <int K>
__global__ __launch_bounds__(256) void gemm_pre_kernel(
    const float* __restrict__ A, const float* __restrict__ Wt,
    const float* __restrict__ bias, float* __restrict__ C) {
    extern __shared__ float sm[];
    float* Asm = sm;              // [128][K]
    float* Bsm = sm + 128 * K;    // [K][128]
    int tid = threadIdx.x;
    int mb = blockIdx.x, nb = blockIdx.y;

    const float* Ag = A + (size_t)mb * 128 * K;
    for (int idx = tid * 4; idx < 128 * K; idx += 1024)
        *(float4*)(Asm + idx) = *(const float4*)(Ag + idx);
    for (int idx = tid * 4; idx < K * 128; idx += 1024) {
        int k = idx >> 7, c = idx & 127;
        *(float4*)(Bsm + idx) = *(const float4*)(Wt + (size_t)k * Gsz + nb * 128 + c);
    }
    __syncthreads();

    int tn = tid & 15, tm = tid >> 4;
    int n0 = tn * 8, m0 = tm * 8;

    u64 acc[8][4];
#pragma unroll
    for (int i = 0; i < 8; ++i)
#pragma unroll
        for (int p = 0; p < 4; ++p) acc[i][p] = 0ull;

#pragma unroll 2
    for (int k = 0; k < K; ++k) {
        float4 bv0 = *(const float4*)(Bsm + k * 128 + n0);
        float4 bv1 = *(const float4*)(Bsm + k * 128 + n0 + 4);
        u64 bp[4];
        bp[0] = pack2(bv0.x, bv0.y); bp[1] = pack2(bv0.z, bv0.w);
        bp[2] = pack2(bv1.x, bv1.y); bp[3] = pack2(bv1.z, bv1.w);
#pragma unroll
        for (int i = 0; i < 8; ++i) {
            float a = Asm[(m0 + i) * K + k];
            u64 ad = pack2(a, a);
#pragma unroll
            for (int p = 0; p < 4; ++p) acc[i][p] = ffma2(ad, bp[p], acc[i][p]);
        }
    }

    float4 bs0 = *(const float4*)(bias + nb * 128 + n0);
    float4 bs1 = *(const float4*)(bias + nb * 128 + n0 + 4);
#pragma unroll
    for (int i = 0; i < 8; ++i) {
        float v[8];
        unpack2(acc[i][0], v[0], v[1]); unpack2(acc[i][1], v[2], v[3]);
        unpack2(acc[i][2], v[4], v[5]); unpack2(acc[i][3], v[6], v[7]);
        size_t row = ((size_t)mb * 128 + m0 + i) * Gsz + nb * 128 + n0;
        *(float4*)(C + row)     = make_float4(v[0]+bs0.x, v[1]+bs0.y, v[2]+bs0.z, v[3]+bs0.w);
        *(float4*)(C + row + 4) = make_float4(v[4]+bs1.x, v[5]+bs1.y, v[6]+bs1.z, v[7]+bs1.w);
    }
}

// One CTA = 4 batch rows, 128 threads, thread j = hidden unit j.
template <bool STORE_ALL>
__global__ __launch_bounds__(128) void lstm_kernel(
    const float* __restrict__ pre, const float* __restrict__ whh_t,
    float* __restrict__ hout) {
    extern __shared__ float smf[];
    float* Wsm = smf;                          // KSM*512 floats
    u64*   hdup = (u64*)(smf + KSM * Gsz);     // [4][128] duplicated h
    int j = threadIdx.x;
    int b0 = blockIdx.x * 4;

    for (int idx = j * 4; idx < KSM * Gsz; idx += 512)
        *(float4*)(Wsm + idx) = *(const float4*)(whh_t + idx);
    float4 wreg[KREG];
#pragma unroll
    for (int r = 0; r < KREG; ++r)
        wreg[r] = *(const float4*)(whh_t + (size_t)(KSM + r) * Gsz + j * 4);

#pragma unroll
    for (int b = 0; b < 4; ++b) hdup[b * Hsz + j] = 0ull;
    float c[4] = {0.f, 0.f, 0.f, 0.f};
    __syncthreads();

    size_t poff[4];
#pragma unroll
    for (int b = 0; b < 4; ++b) poff[b] = (size_t)(b0 + b) * Ssz * Gsz;

    float pc[4][4], pn[4][4];
#pragma unroll
    for (int b = 0; b < 4; ++b)
#pragma unroll
        for (int g = 0; g < 4; ++g)
            pc[b][g] = pre[poff[b] + j + g * Hsz];

    for (int t = 0; t < Ssz; ++t) {
        u64 accif[4], accgo[4];
#pragma unroll
        for (int b = 0; b < 4; ++b) {
            accif[b] = pack2(pc[b][0], pc[b][1]);
            accgo[b] = pack2(pc[b][2], pc[b][3]);
        }
        int tn1 = (t + 1 < Ssz) ? (t + 1) : (Ssz - 1);
#pragma unroll
        for (int b = 0; b < 4; ++b)
#pragma unroll
            for (int g = 0; g < 4; ++g)
                pn[b][g] = pre[poff[b] + (size_t)tn1 * Gsz + j + g * Hsz];

#pragma unroll 3
        for (int k = 0; k < KSM; ++k) {
            float4 w = *(const float4*)(Wsm + k * Gsz + j * 4);
            u64 wif = pack2(w.x, w.y);
            u64 wgo = pack2(w.z, w.w);
#pragma unroll
            for (int b = 0; b < 4; ++b) {
                u64 hd = hdup[b * Hsz + k];
                accif[b] = ffma2(wif, hd, accif[b]);
                accgo[b] = ffma2(wgo, hd, accgo[b]);
            }
        }
#pragma unroll
        for (int r = 0; r < KREG; ++r) {
            u64 wif = pack2(wreg[r].x, wreg[r].y);
            u64 wgo = pack2(wreg[r].z, wreg[r].w);
#pragma unroll
            for (int b = 0; b < 4; ++b) {
                u64 hd = hdup[b * Hsz + KSM + r];
                accif[b] = ffma2(wif, hd, accif[b]);
                accgo[b] = ffma2(wgo, hd, accgo[b]);
            }
        }
        __syncthreads();

#pragma unroll
        for (int b = 0; b < 4; ++b) {
            float ip, fp, gp, op;
            unpack2(accif[b], ip, fp);
            unpack2(accgo[b], gp, op);
            float ig = sigmoidf_(ip);
            float fg = sigmoidf_(fp);
            float gg = tanhf_(gp);
            float og = sigmoidf_(op);
            c[b] = fg * c[b] + ig * gg;
            float h = og * tanhf_(c[b]);
            hdup[b * Hsz + j] = pack2(h, h);
            if (STORE_ALL) {
                hout[((size_t)(b0 + b) * Ssz + t) * Hsz + j] = h;
            } else if (t == Ssz - 1) {
                hout[(size_t)(b0 + b) * Hsz + j] = h;
            }
        }
        __syncthreads();

#pragma unroll
        for (int b = 0; b < 4; ++b)
#pragma unroll
            for (int g = 0; g < 4; ++g) pc[b][g] = pn[b][g];
    }
}

__global__ void head_kernel(const float* __restrict__ h2, const float* __restrict__ Wlin,
                            const float* __restrict__ blin, float* __restrict__ out) {
    int lane = threadIdx.x & 31;
    int warp = (blockIdx.x * blockDim.x + threadIdx.x) >> 5;
    int nw = (gridDim.x * blockDim.x) >> 5;
    float4 wv = ((const float4*)Wlin)[lane];
    float bl = blin[0];
    for (int b = warp; b < Bsz; b += nw) {
        float4 hv = ((const float4*)(h2 + (size_t)b * Hsz))[lane];
        float s = hv.x * wv.x + hv.y * wv.y + hv.z * wv.z + hv.w * wv.w;
#pragma unroll
        for (int o = 16; o; o >>= 1) s += __shfl_xor_sync(0xFFFFFFFFu, s, o);
        if (lane == 0) out[b] = s + bl;
    }
}

extern "C" void kernel_launch(void* const* d_in, const int* in_sizes, int n_in,
                              void* d_out, int out_size) {
    const float* x    = (const float*)d_in[0];
    const float* Wih0 = (const float*)d_in[1];
    const float* Whh0 = (const float*)d_in[2];
    const float* bih0 = (const float*)d_in[3];
    const float* bhh0 = (const float*)d_in[4];
    const float* Wih1 = (const float*)d_in[5];
    const float* Whh1 = (const float*)d_in[6];
    const float* bih1 = (const float*)d_in[7];
    const float* bhh1 = (const float*)d_in[8];
    const float* Wlin = (const float*)d_in[9];
    const float* blin = (const float*)d_in[10];
    float* out = (float*)d_out;

    static bool attr_done = false;
    if (!attr_done) {
        cudaFuncSetAttribute(gemm_pre_kernel<Dsz>, cudaFuncAttributeMaxDynamicSharedMemorySize, 64 * 1024);
        cudaFuncSetAttribute(gemm_pre_kernel<Hsz>, cudaFuncAttributeMaxDynamicSharedMemorySize, 128 * 1024);
        cudaFuncSetAttribute(lstm_kernel<true>,  cudaFuncAttributeMaxDynamicSharedMemorySize, LSTM_SMEM);
        cudaFuncSetAttribute(lstm_kernel<false>, cudaFuncAttributeMaxDynamicSharedMemorySize, LSTM_SMEM);
        attr_done = true;
    }

    void *p_pre, *p_h1, *p_h2, *p_whh, *p_w0, *p_w1, *p_bias;
    cudaGetSymbolAddress(&p_pre,  g_pre);
    cudaGetSymbolAddress(&p_h1,   g_h1);
    cudaGetSymbolAddress(&p_h2,   g_h2last);
    cudaGetSymbolAddress(&p_whh,  g_whh_t);
    cudaGetSymbolAddress(&p_w0,   g_wih0_t);
    cudaGetSymbolAddress(&p_w1,   g_wih1_t);
    cudaGetSymbolAddress(&p_bias, g_bias);

    prep_kernel<<<128, 512>>>(Wih0, Whh0, bih0, bhh0, Wih1, Whh1, bih1, bhh1);

    dim3 ggrid(Bsz * Ssz / 128, Gsz / 128);

    // layer 0 pre-activations: x(BS x 64) @ W_ih0^T + bias0
    gemm_pre_kernel<Dsz><<<ggrid, 256, 64 * 1024>>>(
        x, (const float*)p_w0, (const float*)p_bias, (float*)p_pre);

    // layer 0 recurrence -> g_h1 (full sequence)
    lstm_kernel<true><<<Bsz / 4, Hsz, LSTM_SMEM>>>(
        (const float*)p_pre, (const float*)p_whh, (float*)p_h1);

    // layer 1 pre-activations: h1(BS x 128) @ W_ih1^T + bias1
    gemm_pre_kernel<Hsz><<<ggrid, 256, 128 * 1024>>>(
        (const float*)p_h1, (const float*)p_w1,
        (const float*)p_bias + Gsz, (float*)p_pre);

    // layer 1 recurrence -> g_h2last (last step only)
    lstm_kernel<false><<<Bsz / 4, Hsz, LSTM_SMEM>>>(
        (const float*)p_pre, (const float*)p_whh + Hsz * Gsz, (float*)p_h2);

    // linear head
    head_kernel<<<8, 256>>>((const float*)p_h2, Wlin, blin, out);
}

// round 4
// speedup vs baseline: 1.6519x; 1.6519x over previous
#include <cuda_runtime.h>
#include <cuda_bf16.h>

#define Bsz 512
#define Ssz 512
#define Dsz 64
#define Hsz 128
#define Gsz 512

// LSTM smem layout (bytes)
#define KSM2 107
#define W_BYTES (KSM2*512*4)            // 219136
#define HD_OFF  W_BYTES                 // hdup2: 4*64*16 = 4096
#define PART_OFF (W_BYTES + 4096)       // partials: 4*128*16 = 8192
#define LSTM2_SMEM (PART_OFF + 8192)    // 231424

typedef unsigned long long u64;
typedef unsigned int u32;

__device__ float g_pre[(size_t)Bsz * Ssz * Gsz];
__device__ float g_h1[(size_t)Bsz * Ssz * Hsz];
__device__ float g_h2last[Bsz * Hsz];
__device__ float g_whh_t[2 * Hsz * Gsz];
__device__ float g_wih0_t[Dsz * Gsz];
__device__ float g_wih1_t[Hsz * Gsz];
__device__ float g_bias[2 * Gsz];

__device__ __forceinline__ u64 pack2(float x, float y) {
    u64 r; asm("mov.b64 %0, {%1,%2};" : "=l"(r) : "f"(x), "f"(y)); return r;
}
__device__ __forceinline__ void unpack2(u64 v, float &x, float &y) {
    asm("mov.b64 {%0,%1}, %2;" : "=f"(x), "=f"(y) : "l"(v));
}
__device__ __forceinline__ u64 ffma2(u64 a, u64 b, u64 c) {
    u64 d; asm("fma.rn.f32x2 %0, %1, %2, %3;" : "=l"(d) : "l"(a), "l"(b), "l"(c));
    return d;
}
__device__ __forceinline__ u64 addf2(u64 a, u64 b) {
    u64 d; asm("add.rn.f32x2 %0, %1, %2;" : "=l"(d) : "l"(a), "l"(b));
    return d;
}
__device__ __forceinline__ u32 smem_u32(const void* p) {
    u32 a; asm("{ .reg .u64 t; cvta.to.shared.u64 t, %1; cvt.u32.u64 %0, t; }" : "=r"(a) : "l"(p));
    return a;
}
__device__ __forceinline__ void lds_v2(u32 a, u64 &x, u64 &y) {
    asm volatile("ld.shared.v2.u64 {%0,%1}, [%2];" : "=l"(x), "=l"(y) : "r"(a));
}
__device__ __forceinline__ u64 lds_64(u32 a) {
    u64 x; asm volatile("ld.shared.u64 %0, [%1];" : "=l"(x) : "r"(a)); return x;
}
__device__ __forceinline__ void sts_v2(u32 a, u64 x, u64 y) {
    asm volatile("st.shared.v2.u64 [%0], {%1,%2};" :: "r"(a), "l"(x), "l"(y));
}
__device__ __forceinline__ void sts_64(u32 a, u64 x) {
    asm volatile("st.shared.u64 [%0], %1;" :: "r"(a), "l"(x));
}
__device__ __forceinline__ float tanh_fast(float x) {
    float y; asm("tanh.approx.f32 %0, %1;" : "=f"(y) : "f"(x)); return y;
}
__device__ __forceinline__ float sig_fast(float x) {
    return fmaf(tanh_fast(0.5f * x), 0.5f, 0.5f);
}

// --------------------------------- prep -------------------------------------
__global__ void prep_kernel(const float* __restrict__ Wih0, const float* __restrict__ Whh0,
                            const float* __restrict__ bih0, const float* __restrict__ bhh0,
                            const float* __restrict__ Wih1, const float* __restrict__ Whh1,
                            const float* __restrict__ bih1, const float* __restrict__ bhh1) {
    int tid = blockIdx.x * blockDim.x + threadIdx.x;
    int nt  = gridDim.x * blockDim.x;
    for (int idx = tid; idx < Hsz * Gsz; idx += nt) {
        int k = idx >> 9;
        int jg = idx & 511;
        int j = jg >> 2, g = jg & 3;
        g_whh_t[idx]             = Whh0[(g * Hsz + j) * Hsz + k];
        g_whh_t[Hsz * Gsz + idx] = Whh1[(g * Hsz + j) * Hsz + k];
        {
            int n = idx & 511;
            g_wih1_t[idx] = Wih1[n * Hsz + k];
        }
        if (idx < Dsz * Gsz) {
            int k0 = idx >> 9, n = idx & 511;
            g_wih0_t[idx] = Wih0[n * Dsz + k0];
        }
        if (idx < Gsz) {
            g_bias[idx]       = bih0[idx] + bhh0[idx];
            g_bias[Gsz + idx] = bih1[idx] + bhh1[idx];
        }
    }
}

// ------------------------------ pre GEMM ------------------------------------
// C[m][n] = sum_k A[m][k]*Wt[k][n] + bias[n].  BM=BN=128, BK=64 chunks.
// smem: Adup (128x64 u64, value duplicated) 64KB + Bsm (64x128 f32) 32KB = 96KB
// -> 2 CTAs/SM.
template <int K>
__global__ __launch_bounds__(256) void gemm_pre_kernel(
    const float* __restrict__ A, const float* __restrict__ Wt,
    const float* __restrict__ bias, float* __restrict__ C) {
    extern __shared__ float sm[];
    u32 sbase = smem_u32(sm);
    u32 adup = sbase;                 // 128*64 u64
    u32 bsm  = sbase + 65536;         // 64*128 f32
    int tid = threadIdx.x;
    int mb = blockIdx.x, nb = blockIdx.y;

    int tn = tid & 15, tm = tid >> 4;
    int n0 = tn * 8, m0 = tm * 8;

    u64 acc[8][4];
#pragma unroll
    for (int i = 0; i < 8; ++i)
#pragma unroll
        for (int p = 0; p < 4; ++p) acc[i][p] = 0ull;

    const int NCH = K / 64;
#pragma unroll
    for (int ch = 0; ch < NCH; ++ch) {
        if (ch) __syncthreads();
        // load A chunk, store duplicated
        const float* Ag = A + (size_t)mb * 128 * K + ch * 64;
#pragma unroll
        for (int it = 0; it < 8; ++it) {
            int idx = tid + it * 256;           // float4 index within 128x64
            int m = idx >> 4, kc = (idx & 15) * 4;
            float4 v = *(const float4*)(Ag + (size_t)m * K + kc);
            u32 dst = adup + (u32)(m * 64 + kc) * 8;
            sts_v2(dst,      pack2(v.x, v.x), pack2(v.y, v.y));
            sts_v2(dst + 16, pack2(v.z, v.z), pack2(v.w, v.w));
        }
        // load B chunk
#pragma unroll
        for (int it = 0; it < 8; ++it) {
            int idx = tid + it * 256;
            int kr = idx >> 5, n4 = (idx & 31) * 4;
            float4 v = *(const float4*)(Wt + (size_t)(ch * 64 + kr) * Gsz + nb * 128 + n4);
            *(float4*)(sm + 16384 + kr * 128 + n4) = v;   // bsm floats start at +65536B
        }
        __syncthreads();

#pragma unroll 2
        for (int k = 0; k < 64; ++k) {
            u64 bp[4];
            lds_v2(bsm + (u32)(k * 128 + n0) * 4,      bp[0], bp[1]);
            lds_v2(bsm + (u32)(k * 128 + n0) * 4 + 16, bp[2], bp[3]);
#pragma unroll
            for (int i = 0; i < 8; ++i) {
                u64 ad = lds_64(adup + (u32)((m0 + i) * 64 + k) * 8);
#pragma unroll
                for (int p = 0; p < 4; ++p) acc[i][p] = ffma2(ad, bp[p], acc[i][p]);
            }
        }
    }

    float4 bs0 = *(const float4*)(bias + nb * 128 + n0);
    float4 bs1 = *(const float4*)(bias + nb * 128 + n0 + 4);
#pragma unroll
    for (int i = 0; i < 8; ++i) {
        float v[8];
        unpack2(acc[i][0], v[0], v[1]); unpack2(acc[i][1], v[2], v[3]);
        unpack2(acc[i][2], v[4], v[5]); unpack2(acc[i][3], v[6], v[7]);
        size_t row = ((size_t)mb * 128 + m0 + i) * Gsz + nb * 128 + n0;
        *(float4*)(C + row)     = make_float4(v[0]+bs0.x, v[1]+bs0.y, v[2]+bs0.z, v[3]+bs0.w);
        *(float4*)(C + row + 4) = make_float4(v[4]+bs1.x, v[5]+bs1.y, v[6]+bs1.z, v[7]+bs1.w);
    }
}

// ------------------------------ LSTM ----------------------------------------
// CTA: 256 threads. half0 (tid<128): k 0..63 + epilogue. half1: k 64..127
// (107..127 from registers). j = tid&127 = hidden unit. 4 batch rows/CTA.
// hdup2[b][k/2]: float4 = (h_k,h_k,h_{k+1},h_{k+1}).
template <bool STORE_ALL>
__global__ __launch_bounds__(256) void lstm_kernel(
    const float* __restrict__ pre, const float* __restrict__ whh_t,
    float* __restrict__ hout) {
    extern __shared__ float smf[];
    u32 sbase = smem_u32(smf);
    int tid = threadIdx.x;
    int j = tid & 127;
    int half = tid >> 7;
    int b0 = blockIdx.x * 4;

    for (int idx = tid * 4; idx < KSM2 * 512; idx += 1024)
        *(float4*)(smf + idx) = *(const float4*)(whh_t + idx);

    u64 wifr[21], wgor[21];
    if (half) {
#pragma unroll
        for (int r = 0; r < 21; ++r) {
            float4 w = *(const float4*)(whh_t + (size_t)(107 + r) * 512 + j * 4);
            wifr[r] = pack2(w.x, w.y);
            wgor[r] = pack2(w.z, w.w);
        }
    }

    u32 hd_base = sbase + HD_OFF;
    u32 part_j  = sbase + PART_OFF + j * 16;
    u32 wrow    = sbase + j * 16;
    u32 hd_slot = hd_base + (((j >> 1)) * 16) + ((j & 1) * 8);

    float c[4] = {0.f, 0.f, 0.f, 0.f};
    if (!half) {
#pragma unroll
        for (int b = 0; b < 4; ++b) sts_64(hd_slot + b * 1024, 0ull);
    }
    __syncthreads();

    size_t poff[4];
#pragma unroll
    for (int b = 0; b < 4; ++b) poff[b] = (size_t)(b0 + b) * Ssz * Gsz;

    float pc[4][4], pn[4][4];
    if (!half) {
#pragma unroll
        for (int b = 0; b < 4; ++b)
#pragma unroll
            for (int g = 0; g < 4; ++g)
                pc[b][g] = pre[poff[b] + j + g * Hsz];
    }

    for (int t = 0; t < Ssz; ++t) {
        u64 aif[4], ago[4];
        if (!half) {
#pragma unroll
            for (int b = 0; b < 4; ++b) {
                aif[b] = pack2(pc[b][0], pc[b][1]);
                ago[b] = pack2(pc[b][2], pc[b][3]);
            }
            int tn1 = (t + 1 < Ssz) ? (t + 1) : (Ssz - 1);
#pragma unroll
            for (int b = 0; b < 4; ++b)
#pragma unroll
                for (int g = 0; g < 4; ++g)
                    pn[b][g] = pre[poff[b] + (size_t)tn1 * Gsz + j + g * Hsz];
        } else {
#pragma unroll
            for (int b = 0; b < 4; ++b) { aif[b] = 0ull; ago[b] = 0ull; }
        }

        if (!half) {
#pragma unroll 4
            for (int i = 0; i < 32; ++i) {          // k = 2i, 2i+1
                u64 w0i, w0g, w1i, w1g;
                lds_v2(wrow + (u32)(2 * i) * 2048,     w0i, w0g);
                lds_v2(wrow + (u32)(2 * i + 1) * 2048, w1i, w1g);
#pragma unroll
                for (int b = 0; b < 4; ++b) {
                    u64 h0, h1;
                    lds_v2(hd_base + (u32)(b * 64 + i) * 16, h0, h1);
                    aif[b] = ffma2(w0i, h0, aif[b]);
                    ago[b] = ffma2(w0g, h0, ago[b]);
                    aif[b] = ffma2(w1i, h1, aif[b]);
                    ago[b] = ffma2(w1g, h1, ago[b]);
                }
            }
        } else {
#pragma unroll 4
            for (int i = 0; i < 21; ++i) {          // k = 64+2i, 65+2i
                int k = 64 + 2 * i;
                u64 w0i, w0g, w1i, w1g;
                lds_v2(wrow + (u32)k * 2048,       w0i, w0g);
                lds_v2(wrow + (u32)(k + 1) * 2048, w1i, w1g);
#pragma unroll
                for (int b = 0; b < 4; ++b) {
                    u64 h0, h1;
                    lds_v2(hd_base + (u32)(b * 64 + 32 + i) * 16, h0, h1);
                    aif[b] = ffma2(w0i, h0, aif[b]);
                    ago[b] = ffma2(w0g, h0, ago[b]);
                    aif[b] = ffma2(w1i, h1, aif[b]);
                    ago[b] = ffma2(w1g, h1, ago[b]);
                }
            }
            {   // k = 106 (smem W), pair 53 slot 0
                u64 wi, wg;
                lds_v2(wrow + 106u * 2048, wi, wg);
#pragma unroll
                for (int b = 0; b < 4; ++b) {
                    u64 h = lds_64(hd_base + (u32)(b * 64 + 53) * 16);
                    aif[b] = ffma2(wi, h, aif[b]);
                    ago[b] = ffma2(wg, h, ago[b]);
                }
            }
            {   // k = 107 (reg 0), pair 53 slot 1
#pragma unroll
                for (int b = 0; b < 4; ++b) {
                    u64 h = lds_64(hd_base + (u32)(b * 64 + 53) * 16 + 8);
                    aif[b] = ffma2(wifr[0], h, aif[b]);
                    ago[b] = ffma2(wgor[0], h, ago[b]);
                }
            }
#pragma unroll
            for (int p = 0; p < 10; ++p) {          // k = 108+2p, 109+2p (regs)
#pragma unroll
                for (int b = 0; b < 4; ++b) {
                    u64 h0, h1;
                    lds_v2(hd_base + (u32)(b * 64 + 54 + p) * 16, h0, h1);
                    aif[b] = ffma2(wifr[1 + 2 * p], h0, aif[b]);
                    ago[b] = ffma2(wgor[1 + 2 * p], h0, ago[b]);
                    aif[b] = ffma2(wifr[2 + 2 * p], h1, aif[b]);
                    ago[b] = ffma2(wgor[2 + 2 * p], h1, ago[b]);
                }
            }
#pragma unroll
            for (int b = 0; b < 4; ++b)
                sts_v2(part_j + b * 2048, aif[b], ago[b]);
        }
        __syncthreads();

        if (!half) {
#pragma unroll
            for (int b = 0; b < 4; ++b) {
                u64 pif, pgo;
                lds_v2(part_j + b * 2048, pif, pgo);
                aif[b] = addf2(aif[b], pif);
                ago[b] = addf2(ago[b], pgo);
                float ip, fp, gp, op;
                unpack2(aif[b], ip, fp);
                unpack2(ago[b], gp, op);
                float ig = sig_fast(ip);
                float fg = sig_fast(fp);
                float gg = tanh_fast(gp);
                float og = sig_fast(op);
                c[b] = fg * c[b] + ig * gg;
                float h = og * tanh_fast(c[b]);
                sts_64(hd_slot + b * 1024, pack2(h, h));
                if (STORE_ALL) {
                    hout[((size_t)(b0 + b) * Ssz + t) * Hsz + j] = h;
                } else if (t == Ssz - 1) {
                    hout[(size_t)(b0 + b) * Hsz + j] = h;
                }
            }
#pragma unroll
            for (int b = 0; b < 4; ++b)
#pragma unroll
                for (int g = 0; g < 4; ++g) pc[b][g] = pn[b][g];
        }
        __syncthreads();
    }
}

// ------------------------------- head ---------------------------------------
__global__ void head_kernel(const float* __restrict__ h2, const float* __restrict__ Wlin,
                            const float* __restrict__ blin, float* __restrict__ out) {
    int lane = threadIdx.x & 31;
    int warp = (blockIdx.x * blockDim.x + threadIdx.x) >> 5;
    int nw = (gridDim.x * blockDim.x) >> 5;
    float4 wv = ((const float4*)Wlin)[lane];
    float bl = blin[0];
    for (int b = warp; b < Bsz; b += nw) {
        float4 hv = ((const float4*)(h2 + (size_t)b * Hsz))[lane];
        float s = hv.x * wv.x + hv.y * wv.y + hv.z * wv.z + hv.w * wv.w;
#pragma unroll
        for (int o = 16; o; o >>= 1) s += __shfl_xor_sync(0xFFFFFFFFu, s, o);
        if (lane == 0) out[b] = s + bl;
    }
}

// ------------------------------ launcher ------------------------------------
extern "C" void kernel_launch(void* const* d_in, const int* in_sizes, int n_in,
                              void* d_out, int out_size) {
    const float* x    = (const float*)d_in[0];
    const float* Wih0 = (const float*)d_in[1];
    const float* Whh0 = (const float*)d_in[2];
    const float* bih0 = (const float*)d_in[3];
    const float* bhh0 = (const float*)d_in[4];
    const float* Wih1 = (const float*)d_in[5];
    const float* Whh1 = (const float*)d_in[6];
    const float* bih1 = (const float*)d_in[7];
    const float* bhh1 = (const float*)d_in[8];
    const float* Wlin = (const float*)d_in[9];
    const float* blin = (const float*)d_in[10];
    float* out = (float*)d_out;

    static bool attr_done = false;
    if (!attr_done) {
        cudaFuncSetAttribute(gemm_pre_kernel<Dsz>, cudaFuncAttributeMaxDynamicSharedMemorySize, 98304);
        cudaFuncSetAttribute(gemm_pre_kernel<Hsz>, cudaFuncAttributeMaxDynamicSharedMemorySize, 98304);
        cudaFuncSetAttribute(lstm_kernel<true>,  cudaFuncAttributeMaxDynamicSharedMemorySize, LSTM2_SMEM);
        cudaFuncSetAttribute(lstm_kernel<false>, cudaFuncAttributeMaxDynamicSharedMemorySize, LSTM2_SMEM);
        attr_done = true;
    }

    void *p_pre, *p_h1, *p_h2, *p_whh, *p_w0, *p_w1, *p_bias;
    cudaGetSymbolAddress(&p_pre,  g_pre);
    cudaGetSymbolAddress(&p_h1,   g_h1);
    cudaGetSymbolAddress(&p_h2,   g_h2last);
    cudaGetSymbolAddress(&p_whh,  g_whh_t);
    cudaGetSymbolAddress(&p_w0,   g_wih0_t);
    cudaGetSymbolAddress(&p_w1,   g_wih1_t);
    cudaGetSymbolAddress(&p_bias, g_bias);

    prep_kernel<<<128, 512>>>(Wih0, Whh0, bih0, bhh0, Wih1, Whh1, bih1, bhh1);

    dim3 ggrid(Bsz * Ssz / 128, Gsz / 128);

    gemm_pre_kernel<Dsz><<<ggrid, 256, 98304>>>(
        x, (const float*)p_w0, (const float*)p_bias, (float*)p_pre);

    lstm_kernel<true><<<Bsz / 4, 256, LSTM2_SMEM>>>(
        (const float*)p_pre, (const float*)p_whh, (float*)p_h1);

    gemm_pre_kernel<Hsz><<<ggrid, 256, 98304>>>(
        (const float*)p_h1, (const float*)p_w1,
        (const float*)p_bias + Gsz, (float*)p_pre);

    lstm_kernel<false><<<Bsz / 4, 256, LSTM2_SMEM>>>(
        (const float*)p_pre, (const float*)p_whh + Hsz * Gsz, (float*)p_h2);

    head_kernel<<<8, 256>>>((const float*)p_h2, Wlin, blin, out);
}